// round 7
// baseline (speedup 1.0000x reference)
#include <cuda_runtime.h>
#include <cstdint>

#define N_NODES 8192
#define F_IN    1024
#define F_OUT   512

// ---------------- device scratch ----------------
__device__ float    g_S [N_NODES * F_OUT];   // seq_fts fp32 (for k2)
// slab-major tf32 copy of seq_fts: g_Bt2[(j>>5)*512 + n][ (j&31) ^ ((n&7)<<2) ]
__device__ unsigned g_Bt2[N_NODES / 32 * F_OUT * 32];
__device__ float    g_f1[N_NODES];
__device__ float    g_f2[N_NODES];

// ---------------- helpers ----------------
__device__ __forceinline__ float fast_exp(float x) {
    float t = x * 1.4426950408889634f;
    t = fminf(fmaxf(t, -126.0f), 126.0f);
    float fi = rintf(t);
    float f  = t - fi;
    float p  =          1.5403530393381609e-4f;
    p = fmaf(p, f, 1.3333558146428443e-3f);
    p = fmaf(p, f, 9.6181291076284772e-3f);
    p = fmaf(p, f, 5.5504108664821580e-2f);
    p = fmaf(p, f, 2.4022650695910071e-1f);
    p = fmaf(p, f, 6.9314718055994531e-1f);
    p = fmaf(p, f, 1.0f);
    int e = (int)fi;
    return p * __int_as_float((e + 127) << 23);
}

__device__ __forceinline__ unsigned tf32_of(float x) {
    unsigned r;
    asm("cvt.rna.tf32.f32 %0, %1;" : "=r"(r) : "f"(x));
    return r;
}

__device__ __forceinline__ void mma_tf32(float* d, const unsigned* a, const unsigned* b) {
    asm volatile(
        "mma.sync.aligned.m16n8k8.row.col.f32.tf32.tf32.f32 "
        "{%0,%1,%2,%3}, {%4,%5,%6,%7}, {%8,%9}, {%0,%1,%2,%3};"
        : "+f"(d[0]), "+f"(d[1]), "+f"(d[2]), "+f"(d[3])
        : "r"(a[0]), "r"(a[1]), "r"(a[2]), "r"(a[3]), "r"(b[0]), "r"(b[1]));
}

#define MBARRIER_INIT(addr, count) \
    asm volatile("mbarrier.init.shared.b64 [%0], %1;" :: "r"((uint32_t)(addr)), "r"((uint32_t)(count)) : "memory")

#define MBARRIER_WAIT_PARITY(mbar_smem_addr, phase_parity) do { \
    uint32_t _mbar = (uint32_t)(mbar_smem_addr); \
    uint32_t _parity = (uint32_t)(phase_parity); \
    uint32_t _done; \
    asm volatile( \
        "{\n\t.reg .pred p;\n\t" \
        "mbarrier.try_wait.parity.acquire.cta.shared::cta.b64 p, [%1], %2;\n\t" \
        "selp.b32 %0, 1, 0, p;\n\t}" \
        : "=r"(_done) : "r"(_mbar), "r"(_parity) : "memory"); \
    if (!_done) { \
        asm volatile( \
            "{\n\t.reg .pred P1;\n\t" \
            "WAIT_LOOP_%=:\n\t" \
            "mbarrier.try_wait.parity.acquire.cta.shared::cta.b64 P1, [%0], %1, 0x989680;\n\t" \
            "@P1 bra.uni WAIT_DONE_%=;\n\t" \
            "bra.uni WAIT_LOOP_%=;\n\t" \
            "WAIT_DONE_%=:\n\t}" \
            :: "r"(_mbar), "r"(_parity) : "memory"); \
    } \
} while(0)

__device__ __forceinline__ void bulk_cp(uint32_t dst_smem, const void* src,
                                        unsigned bytes, uint32_t mbar) {
    asm volatile(
        "cp.async.bulk.shared::cta.global.mbarrier::complete_tx::bytes [%0], [%1], %2, [%3];"
        :: "r"(dst_smem), "l"(src), "r"(bytes), "r"(mbar) : "memory");
}
__device__ __forceinline__ void mbar_expect(uint32_t mbar, unsigned bytes) {
    asm volatile("mbarrier.arrive.expect_tx.shared.b64 _, [%0], %1;"
                 :: "r"(mbar), "r"(bytes) : "memory");
}

// ---------------- K1: seq_fts = x @ seq_W.T (single tf32) ------------------
__global__ __launch_bounds__(256) void k1_seqfts(const float* __restrict__ X,
                                                 const float* __restrict__ W) {
    __shared__ float As[128][36];
    __shared__ float Bs[64][36];
    const int tid = threadIdx.x;
    const int m0 = blockIdx.y * 128;
    const int n0 = blockIdx.x * 64;
    const int warp = tid >> 5, lane = tid & 31;
    const int grp = lane >> 2, tig = lane & 3;
    const int wm = warp & 3, wn = warp >> 2;
    const int lr = tid >> 3;
    const int lc = (tid & 7) << 2;

    float d[2][4][4];
#pragma unroll
    for (int i = 0; i < 2; i++)
#pragma unroll
        for (int j = 0; j < 4; j++)
#pragma unroll
            for (int q = 0; q < 4; q++) d[i][j][q] = 0.0f;

    for (int k0 = 0; k0 < F_IN; k0 += 32) {
#pragma unroll
        for (int p = 0; p < 4; p++) {
            float4 v = *(const float4*)&X[(size_t)(m0 + lr + p * 32) * F_IN + k0 + lc];
            *(float4*)&As[lr + p * 32][lc] = v;
        }
#pragma unroll
        for (int p = 0; p < 2; p++) {
            float4 v = *(const float4*)&W[(size_t)(n0 + lr + p * 32) * F_IN + k0 + lc];
            *(float4*)&Bs[lr + p * 32][lc] = v;
        }
        __syncthreads();
#pragma unroll
        for (int kk = 0; kk < 32; kk += 8) {
            unsigned ah[2][4];
#pragma unroll
            for (int mt = 0; mt < 2; mt++) {
                int rb = wm * 32 + mt * 16;
                ah[mt][0] = tf32_of(As[rb + grp][kk + tig]);
                ah[mt][1] = tf32_of(As[rb + grp + 8][kk + tig]);
                ah[mt][2] = tf32_of(As[rb + grp][kk + tig + 4]);
                ah[mt][3] = tf32_of(As[rb + grp + 8][kk + tig + 4]);
            }
            unsigned bh[4][2];
#pragma unroll
            for (int nt = 0; nt < 4; nt++) {
                int cb = wn * 32 + nt * 8;
                bh[nt][0] = tf32_of(Bs[cb + grp][kk + tig]);
                bh[nt][1] = tf32_of(Bs[cb + grp][kk + tig + 4]);
            }
#pragma unroll
            for (int mt = 0; mt < 2; mt++)
#pragma unroll
                for (int nt = 0; nt < 4; nt++)
                    mma_tf32(d[mt][nt], ah[mt], bh[nt]);
        }
        __syncthreads();
    }
#pragma unroll
    for (int mt = 0; mt < 2; mt++)
#pragma unroll
        for (int nt = 0; nt < 4; nt++) {
            int r = m0 + wm * 32 + mt * 16 + grp;
            int c = n0 + wn * 32 + nt * 8 + tig * 2;
            size_t i00 = (size_t)r * F_OUT + c;
            size_t i10 = (size_t)(r + 8) * F_OUT + c;
            g_S[i00]     = d[mt][nt][0];
            g_S[i00 + 1] = d[mt][nt][1];
            g_S[i10]     = d[mt][nt][2];
            g_S[i10 + 1] = d[mt][nt][3];
            // slab-major swizzled tf32 copy for k4's bulk loads
            size_t slab = (size_t)(r >> 5);
            int w = r & 31;                       // <= 23, so w+8 <= 31
            size_t b0 = (slab * 512 + c) * 32;
            size_t b1 = (slab * 512 + c + 1) * 32;
            int x0 = (c & 7) << 2, x1 = ((c + 1) & 7) << 2;
            g_Bt2[b0 + (w ^ x0)]       = tf32_of(d[mt][nt][0]);
            g_Bt2[b0 + ((w + 8) ^ x0)] = tf32_of(d[mt][nt][2]);
            g_Bt2[b1 + (w ^ x1)]       = tf32_of(d[mt][nt][1]);
            g_Bt2[b1 + ((w + 8) ^ x1)] = tf32_of(d[mt][nt][3]);
        }
}

// ---------------- K2: f1/f2 projections -------------------------------------
__global__ __launch_bounds__(256) void k2_fvec(const float* __restrict__ f1w,
                                               const float* __restrict__ f1b,
                                               const float* __restrict__ f2w,
                                               const float* __restrict__ f2b) {
    int row = blockIdx.x * 8 + (threadIdx.x >> 5);
    int lane = threadIdx.x & 31;
    const float* Sr = g_S + (size_t)row * F_OUT;
    float s1 = 0.f, s2 = 0.f;
    for (int c = lane; c < F_OUT; c += 32) {
        float v = Sr[c];
        s1 = fmaf(v, f1w[c], s1);
        s2 = fmaf(v, f2w[c], s2);
    }
#pragma unroll
    for (int o = 16; o > 0; o >>= 1) {
        s1 += __shfl_xor_sync(0xffffffff, s1, o);
        s2 += __shfl_xor_sync(0xffffffff, s2, o);
    }
    if (lane == 0) {
        g_f1[row] = s1 + f1b[0];
        g_f2[row] = s2 + f2b[0];
    }
}

// ---------------- K3: RWR ----------------------------------------------------
__global__ __launch_bounds__(256) void k3_rwr(const int* __restrict__ adj_ad,
                                              float* __restrict__ out_ri,
                                              int write_ri) {
    const int i = blockIdx.x;
    const int tid = threadIdx.x;
    const int4* crow = (const int4*)(adj_ad + (size_t)i * N_NODES);
    int cnt = 0;
    for (int j4 = tid; j4 < N_NODES / 4; j4 += 256) {
        int4 c = crow[j4];
        cnt += (c.x == 2 || c.x == 3);
        cnt += (c.y == 2 || c.y == 3);
        cnt += (c.z == 2 || c.z == 3);
        cnt += (c.w == 2 || c.w == 3);
    }
    __shared__ int sc[256];
    sc[tid] = cnt;
    __syncthreads();
    for (int s = 128; s > 0; s >>= 1) {
        if (tid < s) sc[tid] += sc[tid + s];
        __syncthreads();
    }
    if (tid == 0 && write_ri) {
        float k = (float)sc[0];
        float den = 1.0f - 0.25f * k;
        float r0, rn;
        if (den == 0.0f) { r0 = 1.0f; rn = 0.5f; }
        else             { r0 = fabsf(1.0f / den); rn = fabsf(0.5f / den); }
        out_ri[2 * i]     = r0;
        out_ri[2 * i + 1] = rn;
    }
}

// ---------------- K4: fused attention GEMM  h = elu(P@S / Z + bias) --------
// All staging via cp.async.bulk (1 UBLKCP for B, 128 for adj rows) -> per-slab
// LDGSTS issue cost eliminated. 3-stage B/adj, 2-stage P, f2 fully staged.
// 256 thr / 8 warps (2M x 4N), warp tile 64x64 (R4 machinery).
#define OFFB   0                        // 3 x 8192 words (B: 256n x 32k, swizzled)
#define OFFA   (3 * 8192)               // 3 x 4096 words (adj: 128 x 32, row-major)
#define OFFP   (OFFA + 3 * 4096)        // 2 x 4608 words (P: 128 x 36 pad)
#define OFFF2  (OFFP + 2 * 4608)        // 8192 words (all of f2)
#define OFFM   (OFFF2 + 8192)           // f1s 128, zrow 128, rzs 128, sbias 256
#define MBAR_B ((OFFM + 640) * 4)       // 3 mbarriers (8B each)
#define K4_SMEM ((OFFM + 640) * 4 + 64)

__device__ __forceinline__ void k4_issue(uint32_t smb, const float* __restrict__ adj,
                                         int m0, int n0, int s, int stage, int lane) {
    uint32_t mb = smb + MBAR_B + stage * 8;
    if (lane == 0) mbar_expect(mb, 49152);      // 32768 (B) + 16384 (adj)
    __syncwarp();
    if (lane == 0)
        bulk_cp(smb + (OFFB + stage * 8192) * 4,
                g_Bt2 + ((size_t)s * 512 + n0) * 32, 32768, mb);
#pragma unroll
    for (int k = 0; k < 4; k++) {
        int r = lane + k * 32;
        bulk_cp(smb + (OFFA + stage * 4096) * 4 + r * 128,
                adj + (size_t)(m0 + r) * N_NODES + s * 32, 128, mb);
    }
}

// one quarter of a P tile: 4 exps for row r = gr + p*32
__device__ __forceinline__ void pgen_chunk(const float* adjS, unsigned* Pn,
                                           const float* f1s, const float4& f2v,
                                           int gr, int gc, int p, float* zacc) {
    int r = gr + p * 32;
    float4 a = *(const float4*)&adjS[r * 32 + gc];
    float f1v = f1s[r];
    float l, e0, e1, e2, e3;
    l = f1v + f2v.x; l = l > 0.f ? l : 0.2f * l; e0 = fast_exp(l + a.x);
    l = f1v + f2v.y; l = l > 0.f ? l : 0.2f * l; e1 = fast_exp(l + a.y);
    l = f1v + f2v.z; l = l > 0.f ? l : 0.2f * l; e2 = fast_exp(l + a.z);
    l = f1v + f2v.w; l = l > 0.f ? l : 0.2f * l; e3 = fast_exp(l + a.w);
    zacc[p] += (e0 + e1) + (e2 + e3);
    uint4 q;
    q.x = tf32_of(e0); q.y = tf32_of(e1); q.z = tf32_of(e2); q.w = tf32_of(e3);
    *(uint4*)&Pn[r * 36 + gc] = q;
}

__global__ __launch_bounds__(256, 1) void k4_attn(const float* __restrict__ adj,
                                                  const float* __restrict__ bias,
                                                  float* __restrict__ out) {
    extern __shared__ float sm[];
    float* f2all = sm + OFFF2;
    float* f1s   = sm + OFFM;
    float* zrow  = sm + OFFM + 128;
    float* rzs   = sm + OFFM + 256;
    float* sbias = sm + OFFM + 384;
    const uint32_t smb = (uint32_t)__cvta_generic_to_shared(sm);

    const int tid = threadIdx.x;
    const int m0 = blockIdx.y * 128;
    const int n0 = blockIdx.x * 256;
    const int warp = tid >> 5, lane = tid & 31;
    const int grp = lane >> 2, tig = lane & 3;
    const int wm = warp >> 2, wn = warp & 3;     // 2M x 4N, warp tile 64x64
    const int gr = tid >> 3;                     // 0..31
    const int gc = (tid & 7) << 2;               // 0..28
    const int bXor = grp << 2;                   // B bank-swizzle per thread

    if (tid < 128) f1s[tid] = g_f1[m0 + tid];
    sbias[tid] = bias[n0 + tid];
#pragma unroll
    for (int k = 0; k < 8; k++) {
        int e = (tid + k * 256) * 4;
        *(float4*)&f2all[e] = *(const float4*)&g_f2[e];
    }
    if (tid == 0) {
        MBARRIER_INIT(smb + MBAR_B, 1);
        MBARRIER_INIT(smb + MBAR_B + 8, 1);
        MBARRIER_INIT(smb + MBAR_B + 16, 1);
    }
    __syncthreads();              // mbars + f2all + f1s visible

    if (warp == 0) {
        k4_issue(smb, adj, m0, n0, 0, 0, lane);
        k4_issue(smb, adj, m0, n0, 1, 1, lane);
    }

    float d[4][8][4];
#pragma unroll
    for (int mt = 0; mt < 4; mt++)
#pragma unroll
        for (int nt = 0; nt < 8; nt++)
#pragma unroll
            for (int q = 0; q < 4; q++) d[mt][nt][q] = 0.0f;
    float zacc[4] = {0.f, 0.f, 0.f, 0.f};

    int bRow[8];
#pragma unroll
    for (int nt = 0; nt < 8; nt++) bRow[nt] = (wn * 64 + nt * 8 + grp) * 32;

    // slab 0 arrived -> pgen(0)
    MBARRIER_WAIT_PARITY(smb + MBAR_B, 0);
    {
        const float* adjS = sm + OFFA;
        unsigned* Pn = (unsigned*)(sm + OFFP);
        float4 f2v = *(const float4*)&f2all[gc];
#pragma unroll
        for (int p = 0; p < 4; p++)
            pgen_chunk(adjS, Pn, f1s, f2v, gr, gc, p, zacc);
    }

    int stw = 1, phw = 0;    // wait target (slab s+1)
    int stv = 2;             // issue stage (slab s+2)
    int stc = 0;             // current B/adj stage (slab s)

    for (int s = 0; s < 256; s++) {
        if (s + 1 < 256) MBARRIER_WAIT_PARITY(smb + MBAR_B + stw * 8, phw);
        __syncthreads();     // publish P(s); all readers of stage stv finished
        if (warp == 0 && s + 2 < 256) k4_issue(smb, adj, m0, n0, s + 2, stv, lane);

        const unsigned* Pc = (const unsigned*)(sm + OFFP + (s & 1) * 4608);
        const unsigned* Bc = (const unsigned*)(sm + OFFB + stc * 8192);
        const float*  adjS1 = sm + OFFA + stw * 4096;
        unsigned*        Pn = (unsigned*)(sm + OFFP + ((s + 1) & 1) * 4608);
        const bool gen = (s + 1 < 256);
        float4 f2v;
        if (gen) f2v = *(const float4*)&f2all[(s + 1) * 32 + gc];

#pragma unroll
        for (int kk8 = 0; kk8 < 4; kk8++) {
            if (gen) pgen_chunk(adjS1, Pn, f1s, f2v, gr, gc, kk8, zacc);

            const int kk = kk8 * 8;
            unsigned a[4][4];
#pragma unroll
            for (int mt = 0; mt < 4; mt++) {
                int rb = wm * 64 + mt * 16;
                a[mt][0] = Pc[(rb + grp) * 36 + kk + tig];
                a[mt][1] = Pc[(rb + grp + 8) * 36 + kk + tig];
                a[mt][2] = Pc[(rb + grp) * 36 + kk + tig + 4];
                a[mt][3] = Pc[(rb + grp + 8) * 36 + kk + tig + 4];
            }
            unsigned b[8][2];
#pragma unroll
            for (int nt = 0; nt < 8; nt++) {
                b[nt][0] = Bc[bRow[nt] + ((kk + tig) ^ bXor)];
                b[nt][1] = Bc[bRow[nt] + ((kk + tig + 4) ^ bXor)];
            }
#pragma unroll
            for (int mt = 0; mt < 4; mt++)
#pragma unroll
                for (int nt = 0; nt < 8; nt++)
                    mma_tf32(d[mt][nt], a[mt], b[nt]);
        }
        // advance ring counters
        stc = stw;
        stw++; if (stw == 3) { stw = 0; phw ^= 1; }
        stv++; if (stv == 3) stv = 0;
    }

    // ---- Z reduction (8 threads per row) ----
#pragma unroll
    for (int m = 1; m < 8; m <<= 1)
#pragma unroll
        for (int p = 0; p < 4; p++)
            zacc[p] += __shfl_xor_sync(0xffffffff, zacc[p], m);
    if ((tid & 7) == 0) {
#pragma unroll
        for (int p = 0; p < 4; p++) zrow[gr + p * 32] = zacc[p];
    }
    __syncthreads();
    if (tid < 128) rzs[tid] = 1.0f / zrow[tid];
    __syncthreads();

    // ---- epilogue: /Z, +bias, ELU ----
#pragma unroll
    for (int mt = 0; mt < 4; mt++) {
        int rl = wm * 64 + mt * 16 + grp;
        float rz0 = rzs[rl], rz1 = rzs[rl + 8];
        int gi = m0 + rl;
#pragma unroll
        for (int nt = 0; nt < 8; nt++) {
            int cl = wn * 64 + nt * 8 + tig * 2;
            int gf = n0 + cl;
            float b0 = sbias[cl], b1 = sbias[cl + 1];
            float v;
            v = fmaf(d[mt][nt][0], rz0, b0);
            out[(size_t)gi * F_OUT + gf]           = v > 0.f ? v : fast_exp(v) - 1.0f;
            v = fmaf(d[mt][nt][1], rz0, b1);
            out[(size_t)gi * F_OUT + gf + 1]       = v > 0.f ? v : fast_exp(v) - 1.0f;
            v = fmaf(d[mt][nt][2], rz1, b0);
            out[(size_t)(gi + 8) * F_OUT + gf]     = v > 0.f ? v : fast_exp(v) - 1.0f;
            v = fmaf(d[mt][nt][3], rz1, b1);
            out[(size_t)(gi + 8) * F_OUT + gf + 1] = v > 0.f ? v : fast_exp(v) - 1.0f;
        }
    }
}

// ---------------- launch ----------------
extern "C" void kernel_launch(void* const* d_in, const int* in_sizes, int n_in,
                              void* d_out, int out_size) {
    const float* x      = (const float*)d_in[0];
    const float* adj    = (const float*)d_in[1];
    const int*   adj_ad = (const int*)d_in[2];
    const float* seq_W  = (const float*)d_in[3];
    const float* f1w    = (const float*)d_in[4];
    const float* f1b    = (const float*)d_in[5];
    const float* f2w    = (const float*)d_in[6];
    const float* f2b    = (const float*)d_in[7];
    const float* bias   = (const float*)d_in[8];
    float* out = (float*)d_out;

    static int smem_set = 0;
    if (!smem_set) {
        cudaFuncSetAttribute(k4_attn, cudaFuncAttributeMaxDynamicSharedMemorySize, K4_SMEM);
        smem_set = 1;
    }

    k1_seqfts<<<dim3(8, 64), 256>>>(x, seq_W);
    k2_fvec<<<N_NODES / 8, 256>>>(f1w, f1b, f2w, f2b);
    int write_ri = (out_size >= N_NODES * F_OUT + 2 * N_NODES) ? 1 : 0;
    k3_rwr<<<N_NODES, 256>>>(adj_ad, out + (size_t)N_NODES * F_OUT, write_ri);
    k4_attn<<<dim3(2, 64), 256, K4_SMEM>>>(adj, bias, out);
}

// round 8
// speedup vs baseline: 1.4616x; 1.4616x over previous
#include <cuda_runtime.h>
#include <cstdint>

#define N_NODES 8192
#define F_IN    1024
#define F_OUT   512

// ---------------- device scratch ----------------
__device__ float    g_S [N_NODES * F_OUT];   // seq_fts fp32 (for k2)
__device__ unsigned g_St[N_NODES * F_OUT];   // seq_fts tf32 bits row-major (for k4)
__device__ float    g_f1[N_NODES];
__device__ float    g_f2[N_NODES];

// ---------------- helpers ----------------
__device__ __forceinline__ float fast_exp(float x) {
    float t = x * 1.4426950408889634f;
    t = fminf(fmaxf(t, -126.0f), 126.0f);
    float fi = rintf(t);
    float f  = t - fi;
    float p  =          1.5403530393381609e-4f;
    p = fmaf(p, f, 1.3333558146428443e-3f);
    p = fmaf(p, f, 9.6181291076284772e-3f);
    p = fmaf(p, f, 5.5504108664821580e-2f);
    p = fmaf(p, f, 2.4022650695910071e-1f);
    p = fmaf(p, f, 6.9314718055994531e-1f);
    p = fmaf(p, f, 1.0f);
    int e = (int)fi;
    return p * __int_as_float((e + 127) << 23);
}

__device__ __forceinline__ unsigned tf32_of(float x) {
    unsigned r;
    asm("cvt.rna.tf32.f32 %0, %1;" : "=r"(r) : "f"(x));
    return r;
}

__device__ __forceinline__ void mma_tf32(float* d, const unsigned* a, const unsigned* b) {
    asm volatile(
        "mma.sync.aligned.m16n8k8.row.col.f32.tf32.tf32.f32 "
        "{%0,%1,%2,%3}, {%4,%5,%6,%7}, {%8,%9}, {%0,%1,%2,%3};"
        : "+f"(d[0]), "+f"(d[1]), "+f"(d[2]), "+f"(d[3])
        : "r"(a[0]), "r"(a[1]), "r"(a[2]), "r"(a[3]), "r"(b[0]), "r"(b[1]));
}

__device__ __forceinline__ void cp16(void* smem_ptr, const void* gptr) {
    unsigned sa = (unsigned)__cvta_generic_to_shared(smem_ptr);
    asm volatile("cp.async.cg.shared.global [%0], [%1], 16;" :: "r"(sa), "l"(gptr));
}
__device__ __forceinline__ void cp_commit() { asm volatile("cp.async.commit_group;"); }
__device__ __forceinline__ void cp_wait2()  { asm volatile("cp.async.wait_group 2;"); }

#define MBARRIER_INIT(addr, count) \
    asm volatile("mbarrier.init.shared.b64 [%0], %1;" :: "r"((uint32_t)(addr)), "r"((uint32_t)(count)) : "memory")

#define MBARRIER_ARRIVE(addr) \
    asm volatile("mbarrier.arrive.release.cta.shared::cta.b64 _, [%0];" :: "r"((uint32_t)(addr)) : "memory")

#define MBARRIER_WAIT_PARITY(mbar_smem_addr, phase_parity) do { \
    uint32_t _mbar = (uint32_t)(mbar_smem_addr); \
    uint32_t _parity = (uint32_t)(phase_parity); \
    uint32_t _done; \
    asm volatile( \
        "{\n\t.reg .pred p;\n\t" \
        "mbarrier.try_wait.parity.acquire.cta.shared::cta.b64 p, [%1], %2;\n\t" \
        "selp.b32 %0, 1, 0, p;\n\t}" \
        : "=r"(_done) : "r"(_mbar), "r"(_parity) : "memory"); \
    if (!_done) { \
        asm volatile( \
            "{\n\t.reg .pred P1;\n\t" \
            "WAIT_LOOP_%=:\n\t" \
            "mbarrier.try_wait.parity.acquire.cta.shared::cta.b64 P1, [%0], %1, 0x989680;\n\t" \
            "@P1 bra.uni WAIT_DONE_%=;\n\t" \
            "bra.uni WAIT_LOOP_%=;\n\t" \
            "WAIT_DONE_%=:\n\t}" \
            :: "r"(_mbar), "r"(_parity) : "memory"); \
    } \
} while(0)

// ---------------- K1: seq_fts = x @ seq_W.T (single tf32) ------------------
__global__ __launch_bounds__(256) void k1_seqfts(const float* __restrict__ X,
                                                 const float* __restrict__ W) {
    __shared__ float As[128][36];
    __shared__ float Bs[64][36];
    const int tid = threadIdx.x;
    const int m0 = blockIdx.y * 128;
    const int n0 = blockIdx.x * 64;
    const int warp = tid >> 5, lane = tid & 31;
    const int grp = lane >> 2, tig = lane & 3;
    const int wm = warp & 3, wn = warp >> 2;
    const int lr = tid >> 3;
    const int lc = (tid & 7) << 2;

    float d[2][4][4];
#pragma unroll
    for (int i = 0; i < 2; i++)
#pragma unroll
        for (int j = 0; j < 4; j++)
#pragma unroll
            for (int q = 0; q < 4; q++) d[i][j][q] = 0.0f;

    for (int k0 = 0; k0 < F_IN; k0 += 32) {
#pragma unroll
        for (int p = 0; p < 4; p++) {
            float4 v = *(const float4*)&X[(size_t)(m0 + lr + p * 32) * F_IN + k0 + lc];
            *(float4*)&As[lr + p * 32][lc] = v;
        }
#pragma unroll
        for (int p = 0; p < 2; p++) {
            float4 v = *(const float4*)&W[(size_t)(n0 + lr + p * 32) * F_IN + k0 + lc];
            *(float4*)&Bs[lr + p * 32][lc] = v;
        }
        __syncthreads();
#pragma unroll
        for (int kk = 0; kk < 32; kk += 8) {
            unsigned ah[2][4];
#pragma unroll
            for (int mt = 0; mt < 2; mt++) {
                int rb = wm * 32 + mt * 16;
                ah[mt][0] = tf32_of(As[rb + grp][kk + tig]);
                ah[mt][1] = tf32_of(As[rb + grp + 8][kk + tig]);
                ah[mt][2] = tf32_of(As[rb + grp][kk + tig + 4]);
                ah[mt][3] = tf32_of(As[rb + grp + 8][kk + tig + 4]);
            }
            unsigned bh[4][2];
#pragma unroll
            for (int nt = 0; nt < 4; nt++) {
                int cb = wn * 32 + nt * 8;
                bh[nt][0] = tf32_of(Bs[cb + grp][kk + tig]);
                bh[nt][1] = tf32_of(Bs[cb + grp][kk + tig + 4]);
            }
#pragma unroll
            for (int mt = 0; mt < 2; mt++)
#pragma unroll
                for (int nt = 0; nt < 4; nt++)
                    mma_tf32(d[mt][nt], ah[mt], bh[nt]);
        }
        __syncthreads();
    }
#pragma unroll
    for (int mt = 0; mt < 2; mt++)
#pragma unroll
        for (int nt = 0; nt < 4; nt++) {
            int r = m0 + wm * 32 + mt * 16 + grp;
            int c = n0 + wn * 32 + nt * 8 + tig * 2;
            size_t i00 = (size_t)r * F_OUT + c;
            size_t i10 = (size_t)(r + 8) * F_OUT + c;
            g_S[i00]     = d[mt][nt][0];
            g_S[i00 + 1] = d[mt][nt][1];
            g_S[i10]     = d[mt][nt][2];
            g_S[i10 + 1] = d[mt][nt][3];
            g_St[i00]     = tf32_of(d[mt][nt][0]);
            g_St[i00 + 1] = tf32_of(d[mt][nt][1]);
            g_St[i10]     = tf32_of(d[mt][nt][2]);
            g_St[i10 + 1] = tf32_of(d[mt][nt][3]);
        }
}

// ---------------- K2: f1/f2 projections -------------------------------------
__global__ __launch_bounds__(256) void k2_fvec(const float* __restrict__ f1w,
                                               const float* __restrict__ f1b,
                                               const float* __restrict__ f2w,
                                               const float* __restrict__ f2b) {
    int row = blockIdx.x * 8 + (threadIdx.x >> 5);
    int lane = threadIdx.x & 31;
    const float* Sr = g_S + (size_t)row * F_OUT;
    float s1 = 0.f, s2 = 0.f;
    for (int c = lane; c < F_OUT; c += 32) {
        float v = Sr[c];
        s1 = fmaf(v, f1w[c], s1);
        s2 = fmaf(v, f2w[c], s2);
    }
#pragma unroll
    for (int o = 16; o > 0; o >>= 1) {
        s1 += __shfl_xor_sync(0xffffffff, s1, o);
        s2 += __shfl_xor_sync(0xffffffff, s2, o);
    }
    if (lane == 0) {
        g_f1[row] = s1 + f1b[0];
        g_f2[row] = s2 + f2b[0];
    }
}

// ---------------- K3: RWR ----------------------------------------------------
__global__ __launch_bounds__(256) void k3_rwr(const int* __restrict__ adj_ad,
                                              float* __restrict__ out_ri,
                                              int write_ri) {
    const int i = blockIdx.x;
    const int tid = threadIdx.x;
    const int4* crow = (const int4*)(adj_ad + (size_t)i * N_NODES);
    int cnt = 0;
    for (int j4 = tid; j4 < N_NODES / 4; j4 += 256) {
        int4 c = crow[j4];
        cnt += (c.x == 2 || c.x == 3);
        cnt += (c.y == 2 || c.y == 3);
        cnt += (c.z == 2 || c.z == 3);
        cnt += (c.w == 2 || c.w == 3);
    }
    __shared__ int sc[256];
    sc[tid] = cnt;
    __syncthreads();
    for (int s = 128; s > 0; s >>= 1) {
        if (tid < s) sc[tid] += sc[tid + s];
        __syncthreads();
    }
    if (tid == 0 && write_ri) {
        float k = (float)sc[0];
        float den = 1.0f - 0.25f * k;
        float r0, rn;
        if (den == 0.0f) { r0 = 1.0f; rn = 0.5f; }
        else             { r0 = fabsf(1.0f / den); rn = fabsf(0.5f / den); }
        out_ri[2 * i]     = r0;
        out_ri[2 * i + 1] = rn;
    }
}

// ---------------- K4: warp-specialized fused attention GEMM -----------------
// 512 thr: warps 0-7 producers (cp.async staging + pgen + Z), warps 8-15
// consumers (pure MMA, 64x32 warp tile). mbarrier full/empty rings, 3-deep.
// No __syncthreads in main loop. M-tile 128, N-tile 128, grid (4,64).
#define BPD   136
#define BSTW  (32 * BPD)               // 4352 words / B stage
#define PSTW  (128 * 36)               // 4608 words / P stage
#define ASTW  (128 * 32)               // 4096 words / adj stage
#define OFFB  0
#define OFFP  (3 * BSTW)
#define OFFA  (OFFP + 3 * PSTW)
#define OFFF2 (OFFA + 3 * ASTW)
#define OFFM  (OFFF2 + 8192)
#define MBAR  ((OFFM + 512) * 4)       // byte offset: full[0..2], empty[0..2]
#define K4_SMEM (MBAR + 64)

__device__ __forceinline__ void k4_issue(float* sm, const float* __restrict__ adj,
                                         int m0, int n0, int s, int ptid) {
    const int st = s % 3;
    float* Bb = sm + OFFB + st * BSTW;
    float* Ab = sm + OFFA + st * ASTW;
    const int j0 = s * 32;
#pragma unroll
    for (int k = 0; k < 4; k++) {                // B: 32j x 128n words
        int idx = ptid + k * 256;
        int r = idx >> 5, c = (idx & 31) << 2;
        cp16(&Bb[r * BPD + c], &g_St[(size_t)(j0 + r) * F_OUT + n0 + c]);
    }
#pragma unroll
    for (int k = 0; k < 4; k++) {                // adj: 128 x 32 (self-mapped)
        int idx = ptid + k * 256;
        int r = idx >> 3, c = (idx & 7) << 2;
        cp16(&Ab[r * 32 + c], &adj[(size_t)(m0 + r) * N_NODES + j0 + c]);
    }
}

__device__ __forceinline__ void pgen_chunk(const float* adjS, unsigned* Pn,
                                           const float* f1s, const float4& f2v,
                                           int gr, int gc, int p, float* zacc) {
    int r = gr + p * 32;
    float4 a = *(const float4*)&adjS[r * 32 + gc];
    float f1v = f1s[r];
    float l, e0, e1, e2, e3;
    l = f1v + f2v.x; l = l > 0.f ? l : 0.2f * l; e0 = fast_exp(l + a.x);
    l = f1v + f2v.y; l = l > 0.f ? l : 0.2f * l; e1 = fast_exp(l + a.y);
    l = f1v + f2v.z; l = l > 0.f ? l : 0.2f * l; e2 = fast_exp(l + a.z);
    l = f1v + f2v.w; l = l > 0.f ? l : 0.2f * l; e3 = fast_exp(l + a.w);
    zacc[p] += (e0 + e1) + (e2 + e3);
    uint4 q;
    q.x = tf32_of(e0); q.y = tf32_of(e1); q.z = tf32_of(e2); q.w = tf32_of(e3);
    *(uint4*)&Pn[r * 36 + gc] = q;
}

__global__ __launch_bounds__(512, 1) void k4_attn(const float* __restrict__ adj,
                                                  const float* __restrict__ bias,
                                                  float* __restrict__ out) {
    extern __shared__ float sm[];
    float* f2all = sm + OFFF2;
    float* f1s   = sm + OFFM;
    float* zrow  = sm + OFFM + 128;
    float* rzs   = sm + OFFM + 256;
    float* sbias = sm + OFFM + 384;    // 128
    const uint32_t smb = (uint32_t)__cvta_generic_to_shared(sm);

    const int tid = threadIdx.x;
    const int m0 = blockIdx.y * 128;
    const int n0 = blockIdx.x * 128;
    const int warp = tid >> 5, lane = tid & 31;

    // common prologue
    if (tid < 128) f1s[tid] = g_f1[m0 + tid];
    if (tid >= 256 && tid < 384) sbias[tid - 256] = bias[n0 + tid - 256];
#pragma unroll
    for (int k = 0; k < 4; k++) {
        int e = (tid + k * 512) * 4;
        *(float4*)&f2all[e] = *(const float4*)&g_f2[e];
    }
    if (tid == 0) {
#pragma unroll
        for (int i = 0; i < 3; i++) {
            MBARRIER_INIT(smb + MBAR + i * 8, 8);        // full[i]
            MBARRIER_INIT(smb + MBAR + 24 + i * 8, 8);   // empty[i]
        }
    }
    __syncthreads();

    if (warp < 8) {
        // ================= PRODUCER =================
        const int gr = tid >> 3, gc = (tid & 7) << 2;
        float zacc[4] = {0.f, 0.f, 0.f, 0.f};

        k4_issue(sm, adj, m0, n0, 0, tid); cp_commit();
        k4_issue(sm, adj, m0, n0, 1, tid); cp_commit();

        for (int t = 0; t < 256; t++) {
            const int x = t % 3;
            if (t >= 1) {
                int y = (t + 2) % 3;                 // stage of slab t-1
                MBARRIER_WAIT_PARITY(smb + MBAR + 24 + y * 8, ((t - 1) / 3) & 1);
            }
            if (t + 2 < 256) k4_issue(sm, adj, m0, n0, t + 2, tid);
            cp_commit();
            cp_wait2();                              // slab t's cp complete

            float4 f2v = *(const float4*)&f2all[t * 32 + gc];
            const float* adjS = sm + OFFA + x * ASTW;
            unsigned* Pn = (unsigned*)(sm + OFFP + x * PSTW);
#pragma unroll
            for (int p = 0; p < 4; p++)
                pgen_chunk(adjS, Pn, f1s, f2v, gr, gc, p, zacc);

            __syncwarp();
            if (lane == 0) MBARRIER_ARRIVE(smb + MBAR + x * 8);   // full[x]
        }
        // Z reduction (8 threads per row share gr)
#pragma unroll
        for (int m = 1; m < 8; m <<= 1)
#pragma unroll
            for (int p = 0; p < 4; p++)
                zacc[p] += __shfl_xor_sync(0xffffffff, zacc[p], m);
        if ((tid & 7) == 0) {
#pragma unroll
            for (int p = 0; p < 4; p++) zrow[gr + p * 32] = zacc[p];
        }
    } else {
        // ================= CONSUMER =================
        const int cw = warp - 8;
        const int wm = cw >> 2, wn = cw & 3;         // 2M x 4N of 64x32
        const int grp = lane >> 2, tig = lane & 3;

        float d[4][4][4];
#pragma unroll
        for (int mt = 0; mt < 4; mt++)
#pragma unroll
            for (int nt = 0; nt < 4; nt++)
#pragma unroll
                for (int q = 0; q < 4; q++) d[mt][nt][q] = 0.0f;

        for (int t = 0; t < 256; t++) {
            const int x = t % 3;
            MBARRIER_WAIT_PARITY(smb + MBAR + x * 8, (t / 3) & 1);   // full[x]

            const unsigned* Pc = (const unsigned*)(sm + OFFP + x * PSTW);
            const unsigned* Bc = (const unsigned*)(sm + OFFB + x * BSTW);
#pragma unroll
            for (int kk8 = 0; kk8 < 4; kk8++) {
                const int kk = kk8 * 8;
                unsigned a[4][4];
#pragma unroll
                for (int mt = 0; mt < 4; mt++) {
                    int rb = wm * 64 + mt * 16;
                    a[mt][0] = Pc[(rb + grp) * 36 + kk + tig];
                    a[mt][1] = Pc[(rb + grp + 8) * 36 + kk + tig];
                    a[mt][2] = Pc[(rb + grp) * 36 + kk + tig + 4];
                    a[mt][3] = Pc[(rb + grp + 8) * 36 + kk + tig + 4];
                }
                unsigned b[4][2];
#pragma unroll
                for (int nt = 0; nt < 4; nt++) {
                    int cb = wn * 32 + nt * 8 + grp;
                    b[nt][0] = Bc[(kk + tig) * BPD + cb];
                    b[nt][1] = Bc[(kk + tig + 4) * BPD + cb];
                }
#pragma unroll
                for (int mt = 0; mt < 4; mt++)
#pragma unroll
                    for (int nt = 0; nt < 4; nt++)
                        mma_tf32(d[mt][nt], a[mt], b[nt]);
            }
            __syncwarp();
            if (lane == 0) MBARRIER_ARRIVE(smb + MBAR + 24 + x * 8);  // empty[x]
        }

        // stash accumulators through the Z sync below via registers (no-op)
        __syncthreads();                    // matches producers' barrier
        // rzs not ready yet at this barrier; second barrier below
        __syncthreads();

        // epilogue: /Z, +bias, ELU
#pragma unroll
        for (int mt = 0; mt < 4; mt++) {
            int rl = wm * 64 + mt * 16 + grp;
            float rz0 = rzs[rl], rz1 = rzs[rl + 8];
            int gi = m0 + rl;
#pragma unroll
            for (int nt = 0; nt < 4; nt++) {
                int cl = wn * 32 + nt * 8 + tig * 2;
                int gf = n0 + cl;
                float b0 = sbias[cl], b1 = sbias[cl + 1];
                float v;
                v = fmaf(d[mt][nt][0], rz0, b0);
                out[(size_t)gi * F_OUT + gf]           = v > 0.f ? v : fast_exp(v) - 1.0f;
                v = fmaf(d[mt][nt][1], rz0, b1);
                out[(size_t)gi * F_OUT + gf + 1]       = v > 0.f ? v : fast_exp(v) - 1.0f;
                v = fmaf(d[mt][nt][2], rz1, b0);
                out[(size_t)(gi + 8) * F_OUT + gf]     = v > 0.f ? v : fast_exp(v) - 1.0f;
                v = fmaf(d[mt][nt][3], rz1, b1);
                out[(size_t)(gi + 8) * F_OUT + gf + 1] = v > 0.f ? v : fast_exp(v) - 1.0f;
            }
        }
        return;
    }

    // producers: publish zrow, compute rzs
    __syncthreads();
    if (tid < 128) rzs[tid] = 1.0f / zrow[tid];
    __syncthreads();
}

// ---------------- launch ----------------
extern "C" void kernel_launch(void* const* d_in, const int* in_sizes, int n_in,
                              void* d_out, int out_size) {
    const float* x      = (const float*)d_in[0];
    const float* adj    = (const float*)d_in[1];
    const int*   adj_ad = (const int*)d_in[2];
    const float* seq_W  = (const float*)d_in[3];
    const float* f1w    = (const float*)d_in[4];
    const float* f1b    = (const float*)d_in[5];
    const float* f2w    = (const float*)d_in[6];
    const float* f2b    = (const float*)d_in[7];
    const float* bias   = (const float*)d_in[8];
    float* out = (float*)d_out;

    static int smem_set = 0;
    if (!smem_set) {
        cudaFuncSetAttribute(k4_attn, cudaFuncAttributeMaxDynamicSharedMemorySize, K4_SMEM);
        smem_set = 1;
    }

    k1_seqfts<<<dim3(8, 64), 256>>>(x, seq_W);
    k2_fvec<<<N_NODES / 8, 256>>>(f1w, f1b, f2w, f2b);
    int write_ri = (out_size >= N_NODES * F_OUT + 2 * N_NODES) ? 1 : 0;
    k3_rwr<<<N_NODES, 256>>>(adj_ad, out + (size_t)N_NODES * F_OUT, write_ri);
    k4_attn<<<dim3(4, 64), 512, K4_SMEM>>>(adj, bias, out);
}

// round 10
// speedup vs baseline: 1.6527x; 1.1308x over previous
#include <cuda_runtime.h>
#include <cstdint>

#define N_NODES 8192
#define F_IN    1024
#define F_OUT   512

// ---------------- device scratch ----------------
__device__ float    g_S [N_NODES * F_OUT];   // seq_fts fp32 (for k2)
// fragment-major tf32 copy of seq_fts for k4's direct B-fragment LDG.128:
// word index for value S[j][n]:
//   (((j>>5)*4 + ((j>>3)&3))*4 + (j&3)) * 1024
//   + ((n>>4)*8 + (n&7)) * 4 + ((n>>3)&1)*2 + ((j>>2)&1)
__device__ unsigned g_Bf[(N_NODES / 32) * 4 * 4 * 1024];
__device__ float    g_f1[N_NODES];
__device__ float    g_f2[N_NODES];

// ---------------- helpers ----------------
__device__ __forceinline__ float fast_exp(float x) {
    float t = x * 1.4426950408889634f;
    t = fminf(fmaxf(t, -126.0f), 126.0f);
    float fi = rintf(t);
    float f  = t - fi;
    float p  =          1.5403530393381609e-4f;
    p = fmaf(p, f, 1.3333558146428443e-3f);
    p = fmaf(p, f, 9.6181291076284772e-3f);
    p = fmaf(p, f, 5.5504108664821580e-2f);
    p = fmaf(p, f, 2.4022650695910071e-1f);
    p = fmaf(p, f, 6.9314718055994531e-1f);
    p = fmaf(p, f, 1.0f);
    int e = (int)fi;
    return p * __int_as_float((e + 127) << 23);
}

__device__ __forceinline__ unsigned tf32_of(float x) {
    unsigned r;
    asm("cvt.rna.tf32.f32 %0, %1;" : "=r"(r) : "f"(x));
    return r;
}

__device__ __forceinline__ void mma_tf32(float* d, const unsigned* a, const unsigned* b) {
    asm volatile(
        "mma.sync.aligned.m16n8k8.row.col.f32.tf32.tf32.f32 "
        "{%0,%1,%2,%3}, {%4,%5,%6,%7}, {%8,%9}, {%0,%1,%2,%3};"
        : "+f"(d[0]), "+f"(d[1]), "+f"(d[2]), "+f"(d[3])
        : "r"(a[0]), "r"(a[1]), "r"(a[2]), "r"(a[3]), "r"(b[0]), "r"(b[1]));
}

__device__ __forceinline__ int bf_idx(int j, int n) {
    return ((((j >> 5) * 4 + ((j >> 3) & 3)) * 4 + (j & 3)) << 10)
         + (((n >> 4) * 8 + (n & 7)) << 2) + (((n >> 3) & 1) << 1) + ((j >> 2) & 1);
}

// ---------------- K1: seq_fts = x @ seq_W.T (single tf32) ------------------
__global__ __launch_bounds__(256) void k1_seqfts(const float* __restrict__ X,
                                                 const float* __restrict__ W) {
    __shared__ float As[128][36];
    __shared__ float Bs[64][36];
    const int tid = threadIdx.x;
    const int m0 = blockIdx.y * 128;
    const int n0 = blockIdx.x * 64;
    const int warp = tid >> 5, lane = tid & 31;
    const int grp = lane >> 2, tig = lane & 3;
    const int wm = warp & 3, wn = warp >> 2;
    const int lr = tid >> 3;
    const int lc = (tid & 7) << 2;

    float d[2][4][4];
#pragma unroll
    for (int i = 0; i < 2; i++)
#pragma unroll
        for (int j = 0; j < 4; j++)
#pragma unroll
            for (int q = 0; q < 4; q++) d[i][j][q] = 0.0f;

    for (int k0 = 0; k0 < F_IN; k0 += 32) {
#pragma unroll
        for (int p = 0; p < 4; p++) {
            float4 v = *(const float4*)&X[(size_t)(m0 + lr + p * 32) * F_IN + k0 + lc];
            *(float4*)&As[lr + p * 32][lc] = v;
        }
#pragma unroll
        for (int p = 0; p < 2; p++) {
            float4 v = *(const float4*)&W[(size_t)(n0 + lr + p * 32) * F_IN + k0 + lc];
            *(float4*)&Bs[lr + p * 32][lc] = v;
        }
        __syncthreads();
#pragma unroll
        for (int kk = 0; kk < 32; kk += 8) {
            unsigned ah[2][4];
#pragma unroll
            for (int mt = 0; mt < 2; mt++) {
                int rb = wm * 32 + mt * 16;
                ah[mt][0] = tf32_of(As[rb + grp][kk + tig]);
                ah[mt][1] = tf32_of(As[rb + grp + 8][kk + tig]);
                ah[mt][2] = tf32_of(As[rb + grp][kk + tig + 4]);
                ah[mt][3] = tf32_of(As[rb + grp + 8][kk + tig + 4]);
            }
            unsigned bh[4][2];
#pragma unroll
            for (int nt = 0; nt < 4; nt++) {
                int cb = wn * 32 + nt * 8;
                bh[nt][0] = tf32_of(Bs[cb + grp][kk + tig]);
                bh[nt][1] = tf32_of(Bs[cb + grp][kk + tig + 4]);
            }
#pragma unroll
            for (int mt = 0; mt < 2; mt++)
#pragma unroll
                for (int nt = 0; nt < 4; nt++)
                    mma_tf32(d[mt][nt], ah[mt], bh[nt]);
        }
        __syncthreads();
    }
#pragma unroll
    for (int mt = 0; mt < 2; mt++)
#pragma unroll
        for (int nt = 0; nt < 4; nt++) {
            int r = m0 + wm * 32 + mt * 16 + grp;
            int c = n0 + wn * 32 + nt * 8 + tig * 2;
            size_t i00 = (size_t)r * F_OUT + c;
            size_t i10 = (size_t)(r + 8) * F_OUT + c;
            g_S[i00]     = d[mt][nt][0];
            g_S[i00 + 1] = d[mt][nt][1];
            g_S[i10]     = d[mt][nt][2];
            g_S[i10 + 1] = d[mt][nt][3];
            g_Bf[bf_idx(r, c)]         = tf32_of(d[mt][nt][0]);
            g_Bf[bf_idx(r, c + 1)]     = tf32_of(d[mt][nt][1]);
            g_Bf[bf_idx(r + 8, c)]     = tf32_of(d[mt][nt][2]);
            g_Bf[bf_idx(r + 8, c + 1)] = tf32_of(d[mt][nt][3]);
        }
}

// ---------------- K2: f1/f2 projections -------------------------------------
__global__ __launch_bounds__(256) void k2_fvec(const float* __restrict__ f1w,
                                               const float* __restrict__ f1b,
                                               const float* __restrict__ f2w,
                                               const float* __restrict__ f2b) {
    int row = blockIdx.x * 8 + (threadIdx.x >> 5);
    int lane = threadIdx.x & 31;
    const float* Sr = g_S + (size_t)row * F_OUT;
    float s1 = 0.f, s2 = 0.f;
    for (int c = lane; c < F_OUT; c += 32) {
        float v = Sr[c];
        s1 = fmaf(v, f1w[c], s1);
        s2 = fmaf(v, f2w[c], s2);
    }
#pragma unroll
    for (int o = 16; o > 0; o >>= 1) {
        s1 += __shfl_xor_sync(0xffffffff, s1, o);
        s2 += __shfl_xor_sync(0xffffffff, s2, o);
    }
    if (lane == 0) {
        g_f1[row] = s1 + f1b[0];
        g_f2[row] = s2 + f2b[0];
    }
}

// ---------------- K3: RWR ----------------------------------------------------
__global__ __launch_bounds__(256) void k3_rwr(const int* __restrict__ adj_ad,
                                              float* __restrict__ out_ri,
                                              int write_ri) {
    const int i = blockIdx.x;
    const int tid = threadIdx.x;
    const int4* crow = (const int4*)(adj_ad + (size_t)i * N_NODES);
    int cnt = 0;
    for (int j4 = tid; j4 < N_NODES / 4; j4 += 256) {
        int4 c = crow[j4];
        cnt += (c.x == 2 || c.x == 3);
        cnt += (c.y == 2 || c.y == 3);
        cnt += (c.z == 2 || c.z == 3);
        cnt += (c.w == 2 || c.w == 3);
    }
    __shared__ int sc[256];
    sc[tid] = cnt;
    __syncthreads();
    for (int s = 128; s > 0; s >>= 1) {
        if (tid < s) sc[tid] += sc[tid + s];
        __syncthreads();
    }
    if (tid == 0 && write_ri) {
        float k = (float)sc[0];
        float den = 1.0f - 0.25f * k;
        float r0, rn;
        if (den == 0.0f) { r0 = 1.0f; rn = 0.5f; }
        else             { r0 = fabsf(1.0f / den); rn = fabsf(0.5f / den); }
        out_ri[2 * i]     = r0;
        out_ri[2 * i + 1] = rn;
    }
}

// ---------------- K4: fused attention GEMM  h = elu(P@S / Z + bias) --------
// No smem staging for B/adj: B fragments via direct LDG.128 from g_Bf
// (prefetched 1 kk8-step ahead; step stride = 1024 uint4), adj via register
// prefetch (1 slab ahead). Only P goes through smem. 256 thr, warp tile 64x64.
#define PSTW (128 * 36)

__device__ __forceinline__ void pgen_chunk(const float4& a, unsigned* Pn,
                                           float f1v, const float4& f2v,
                                           int r, int gc, float* zacc) {
    float l, e0, e1, e2, e3;
    l = f1v + f2v.x; l = l > 0.f ? l : 0.2f * l; e0 = fast_exp(l + a.x);
    l = f1v + f2v.y; l = l > 0.f ? l : 0.2f * l; e1 = fast_exp(l + a.y);
    l = f1v + f2v.z; l = l > 0.f ? l : 0.2f * l; e2 = fast_exp(l + a.z);
    l = f1v + f2v.w; l = l > 0.f ? l : 0.2f * l; e3 = fast_exp(l + a.w);
    *zacc += (e0 + e1) + (e2 + e3);
    uint4 q;
    q.x = tf32_of(e0); q.y = tf32_of(e1); q.z = tf32_of(e2); q.w = tf32_of(e3);
    *(uint4*)&Pn[r * 36 + gc] = q;
}

__global__ __launch_bounds__(256, 1) void k4_attn(const float* __restrict__ adj,
                                                  const float* __restrict__ bias,
                                                  float* __restrict__ out) {
    __shared__ float sm[2 * PSTW + 640];
    float* f1s   = sm + 2 * PSTW;
    float* zrow  = sm + 2 * PSTW + 128;
    float* rzs   = sm + 2 * PSTW + 256;
    float* sbias = sm + 2 * PSTW + 384;    // 256

    const int tid = threadIdx.x;
    const int m0 = blockIdx.y * 128;
    const int n0 = blockIdx.x * 256;
    const int warp = tid >> 5, lane = tid & 31;
    const int grp = lane >> 2, tig = lane & 3;
    const int wm = warp >> 2, wn = warp & 3;     // 2M x 4N, warp tile 64x64
    const int gr = tid >> 3;                     // 0..31 (pgen row base)
    const int gc = (tid & 7) << 2;               // 0..28 (pgen col)

    if (tid < 128) f1s[tid] = g_f1[m0 + tid];
    sbias[tid] = bias[n0 + tid];
    __syncthreads();

    float d[4][8][4];
#pragma unroll
    for (int mt = 0; mt < 4; mt++)
#pragma unroll
        for (int nt = 0; nt < 8; nt++)
#pragma unroll
            for (int q = 0; q < 4; q++) d[mt][nt][q] = 0.0f;
    float zacc[4] = {0.f, 0.f, 0.f, 0.f};

    // per-thread adj base (row gr + p*32, col gc); slab offset added at use
    const float* adjb = adj + (size_t)(m0 + gr) * N_NODES + gc;
    float f1v[4];
#pragma unroll
    for (int p = 0; p < 4; p++) f1v[p] = f1s[gr + p * 32];

    // B fragment pointer: 256 uint4 per (slab,kk8,tig) block; one (slab,kk8)
    // step = 4 tig blocks = 1024 uint4.
    const uint4* qB = (const uint4*)g_Bf + (size_t)tig * 256
                    + ((n0 >> 4) + wn * 4) * 8 + grp;
    uint4 bb[4], nb[4];
#pragma unroll
    for (int tt = 0; tt < 4; tt++) bb[tt] = qB[tt * 8];   // step u=0
    const uint4* qn = qB + 1024;                          // step u=1

    // adj/f2 prefetch for slab 0, pgen(0), then prefetch slab 1
    float4 adjv[4];
#pragma unroll
    for (int p = 0; p < 4; p++) adjv[p] = *(const float4*)(adjb + p * 32 * N_NODES);
    float4 f2v = *(const float4*)&g_f2[gc];
    {
        unsigned* Pn = (unsigned*)sm;                     // P buffer 0
#pragma unroll
        for (int p = 0; p < 4; p++) {
            pgen_chunk(adjv[p], Pn, f1v[p], f2v, gr + p * 32, gc, &zacc[p]);
            adjv[p] = *(const float4*)(adjb + p * 32 * N_NODES + 32);
        }
    }
    f2v = *(const float4*)&g_f2[32 + gc];

    for (int s = 0; s < 256; s++) {
        __syncthreads();   // publish P(s) [written as P(s+1) last iter]; free P(s+1) buf

        const unsigned* Pc = (const unsigned*)sm + (s & 1) * PSTW;
        unsigned*       Pn = (unsigned*)sm + ((s + 1) & 1) * PSTW;
        const bool gen = (s + 1 < 256);
        const int jn2 = (s + 2) * 32;

#pragma unroll
        for (int kk8 = 0; kk8 < 4; kk8++) {
            // prefetch B fragments for next step (stride 1024 uint4 per step)
            if ((kk8 < 3) || (s < 255)) {
#pragma unroll
                for (int tt = 0; tt < 4; tt++) nb[tt] = qn[tt * 8];
            }
            // pgen chunk kk8 of slab s+1 (FMA pipe, overlaps MMA)
            if (gen) {
                pgen_chunk(adjv[kk8], Pn, f1v[kk8], f2v, gr + kk8 * 32, gc, &zacc[kk8]);
                if (s < 254)
                    adjv[kk8] = *(const float4*)(adjb + kk8 * 32 * N_NODES + jn2);
            }

            const int kk = kk8 * 8;
            unsigned a[4][4];
#pragma unroll
            for (int mt = 0; mt < 4; mt++) {
                int rb = wm * 64 + mt * 16;
                a[mt][0] = Pc[(rb + grp) * 36 + kk + tig];
                a[mt][1] = Pc[(rb + grp + 8) * 36 + kk + tig];
                a[mt][2] = Pc[(rb + grp) * 36 + kk + tig + 4];
                a[mt][3] = Pc[(rb + grp + 8) * 36 + kk + tig + 4];
            }
#pragma unroll
            for (int tt = 0; tt < 4; tt++) {
                unsigned blo[2] = {bb[tt].x, bb[tt].y};
                unsigned bhi[2] = {bb[tt].z, bb[tt].w};
#pragma unroll
                for (int mt = 0; mt < 4; mt++) {
                    mma_tf32(d[mt][2 * tt],     a[mt], blo);
                    mma_tf32(d[mt][2 * tt + 1], a[mt], bhi);
                }
            }
#pragma unroll
            for (int tt = 0; tt < 4; tt++) bb[tt] = nb[tt];
            qn += 1024;
        }
        if (gen && s < 254)
            f2v = *(const float4*)&g_f2[jn2 + gc];
    }

    // ---- Z reduction (8 threads per row) ----
#pragma unroll
    for (int m = 1; m < 8; m <<= 1)
#pragma unroll
        for (int p = 0; p < 4; p++)
            zacc[p] += __shfl_xor_sync(0xffffffff, zacc[p], m);
    if ((tid & 7) == 0) {
#pragma unroll
        for (int p = 0; p < 4; p++) zrow[gr + p * 32] = zacc[p];
    }
    __syncthreads();
    if (tid < 128) rzs[tid] = 1.0f / zrow[tid];
    __syncthreads();

    // ---- epilogue: /Z, +bias, ELU ----
#pragma unroll
    for (int mt = 0; mt < 4; mt++) {
        int rl = wm * 64 + mt * 16 + grp;
        float rz0 = rzs[rl], rz1 = rzs[rl + 8];
        int gi = m0 + rl;
#pragma unroll
        for (int nt = 0; nt < 8; nt++) {
            int cl = wn * 64 + nt * 8 + tig * 2;
            int gf = n0 + cl;
            float b0 = sbias[cl], b1 = sbias[cl + 1];
            float v;
            v = fmaf(d[mt][nt][0], rz0, b0);
            out[(size_t)gi * F_OUT + gf]           = v > 0.f ? v : fast_exp(v) - 1.0f;
            v = fmaf(d[mt][nt][1], rz0, b1);
            out[(size_t)gi * F_OUT + gf + 1]       = v > 0.f ? v : fast_exp(v) - 1.0f;
            v = fmaf(d[mt][nt][2], rz1, b0);
            out[(size_t)(gi + 8) * F_OUT + gf]     = v > 0.f ? v : fast_exp(v) - 1.0f;
            v = fmaf(d[mt][nt][3], rz1, b1);
            out[(size_t)(gi + 8) * F_OUT + gf + 1] = v > 0.f ? v : fast_exp(v) - 1.0f;
        }
    }
}

// ---------------- launch ----------------
extern "C" void kernel_launch(void* const* d_in, const int* in_sizes, int n_in,
                              void* d_out, int out_size) {
    const float* x      = (const float*)d_in[0];
    const float* adj    = (const float*)d_in[1];
    const int*   adj_ad = (const int*)d_in[2];
    const float* seq_W  = (const float*)d_in[3];
    const float* f1w    = (const float*)d_in[4];
    const float* f1b    = (const float*)d_in[5];
    const float* f2w    = (const float*)d_in[6];
    const float* f2b    = (const float*)d_in[7];
    const float* bias   = (const float*)d_in[8];
    float* out = (float*)d_out;

    k1_seqfts<<<dim3(8, 64), 256>>>(x, seq_W);
    k2_fvec<<<N_NODES / 8, 256>>>(f1w, f1b, f2w, f2b);
    int write_ri = (out_size >= N_NODES * F_OUT + 2 * N_NODES) ? 1 : 0;
    k3_rwr<<<N_NODES, 256>>>(adj_ad, out + (size_t)N_NODES * F_OUT, write_ri);
    k4_attn<<<dim3(2, 64), 256>>>(adj, bias, out);
}